// round 4
// baseline (speedup 1.0000x reference)
#include <cuda_runtime.h>
#include <cuda_bf16.h>

#define OUT_CH 128
#define MAX_EDGES 8192
#define GROUPS_PER_THREAD 8   // int4 groups per thread in hist kernel

// Packed per-edge histogram: count of token t in 16-bit field t.
// Zero-initialized at module load; kernel B re-zeros each entry after use,
// so every kernel_launch call (correctness run + each graph replay) starts
// from zeros. Per-field totals <= segment length (~400) << 65536: no carry.
__device__ unsigned long long g_hist[MAX_EDGES];

__global__ void __launch_bounds__(256)
hist_kernel(const int4* __restrict__ tokens4,
            const int4* __restrict__ segs4,
            int n4) {
    const int base = blockIdx.x * (blockDim.x * GROUPS_PER_THREAD);

    int cur = -1;
    unsigned long long acc = 0ull;

#pragma unroll
    for (int i = 0; i < GROUPS_PER_THREAD; i++) {
        // Coalesced: consecutive lanes -> consecutive int4.
        const int j = base + i * blockDim.x + threadIdx.x;
        if (j < n4) {
            const int4 t = tokens4[j];
            const int4 s = segs4[j];
            if (s.x == s.w) {                       // sorted -> all 4 equal
                if (s.x != cur) {
                    if (cur >= 0) atomicAdd(&g_hist[cur], acc);
                    cur = s.x; acc = 0ull;
                }
                acc += (1ull << (t.x * 16)) + (1ull << (t.y * 16))
                     + (1ull << (t.z * 16)) + (1ull << (t.w * 16));
            } else {                                // rare: boundary inside group
                const int ss[4] = {s.x, s.y, s.z, s.w};
                const int tt[4] = {t.x, t.y, t.z, t.w};
#pragma unroll
                for (int k = 0; k < 4; k++) {
                    if (ss[k] != cur) {
                        if (cur >= 0) atomicAdd(&g_hist[cur], acc);
                        cur = ss[k]; acc = 0ull;
                    }
                    acc += 1ull << (tt[k] * 16);
                }
            }
        }
    }
    if (cur >= 0) atomicAdd(&g_hist[cur], acc);
}

// One warp per edge: unpack hist, write the 128-channel mean row (float4 per
// lane, fully coalesced), then zero the hist entry for the next replay.
__global__ void __launch_bounds__(256)
out_kernel(const float* __restrict__ emb,   // [4][128]
           float* __restrict__ out,         // [E][128]
           int n_edges) {
    const int e    = (blockIdx.x * blockDim.x + threadIdx.x) >> 5;
    const int lane = threadIdx.x & 31;
    if (e >= n_edges) return;

    const unsigned long long h = g_hist[e];   // broadcast load across the warp
    __syncwarp();
    if (lane == 0) g_hist[e] = 0ull;          // restore invariant for next call

    const float f0 = (float)((unsigned)(h       ) & 0xFFFFu);
    const float f1 = (float)((unsigned)(h >> 16 ) & 0xFFFFu);
    const float f2 = (float)((unsigned)(h >> 32 ) & 0xFFFFu);
    const float f3 = (float)((unsigned)(h >> 48 ) & 0xFFFFu);
    const float inv = 1.0f / fmaxf(f0 + f1 + f2 + f3, 1.0f);

    const int d = lane * 4;
    const float4 e0 = *(const float4*)(emb + 0 * OUT_CH + d);
    const float4 e1 = *(const float4*)(emb + 1 * OUT_CH + d);
    const float4 e2 = *(const float4*)(emb + 2 * OUT_CH + d);
    const float4 e3 = *(const float4*)(emb + 3 * OUT_CH + d);

    float4 r;
    r.x = (f0 * e0.x + f1 * e1.x + f2 * e2.x + f3 * e3.x) * inv;
    r.y = (f0 * e0.y + f1 * e1.y + f2 * e2.y + f3 * e3.y) * inv;
    r.z = (f0 * e0.z + f1 * e1.z + f2 * e2.z + f3 * e3.z) * inv;
    r.w = (f0 * e0.w + f1 * e1.w + f2 * e2.w + f3 * e3.w) * inv;

    *(float4*)(out + (long long)e * OUT_CH + d) = r;
}

extern "C" void kernel_launch(void* const* d_in, const int* in_sizes, int n_in,
                              void* d_out, int out_size) {
    // Inputs: 0 overlap_similarity f32[E], 1 overlap_length f32[E],
    //         2 tokens i32[T], 3 segment_ids i32[T], 4 embedding f32[4*128],
    //         5 n_edges
    const int*   tokens = (const int*)d_in[2];
    const int*   segs   = (const int*)d_in[3];
    const float* emb    = (const float*)d_in[4];
    float*       out    = (float*)d_out;

    const int total_tokens = in_sizes[2];
    const int n_edges      = out_size / OUT_CH;

    // Kernel A: streaming histogram over int4 groups.
    {
        const int n4 = total_tokens / 4;   // 524288 (T is a multiple of 4)
        const int threads = 256;
        const int per_block = threads * GROUPS_PER_THREAD;
        const int blocks = (n4 + per_block - 1) / per_block;   // 256
        hist_kernel<<<blocks, threads>>>((const int4*)tokens,
                                         (const int4*)segs, n4);
    }

    // Kernel B: epilogue + hist reset.
    {
        const int threads = 256;           // 8 warps -> 8 edges per block
        const int blocks = (n_edges * 32 + threads - 1) / threads;
        out_kernel<<<blocks, threads>>>(emb, out, n_edges);
    }
}